// round 17
// baseline (speedup 1.0000x reference)
#include <cuda_runtime.h>
#include <cuda_fp16.h>
#include <cstdint>
#include <math.h>

#define NS 2048      // speakers
#define NG 8         // utts per speaker
#define ND 128       // embed dim
#define NR (NS*NG)   // 16384 rows
#define KB 128       // bytes per row (int8, K=128)
#define BM 128
#define BN 64
#define NTILES (NS/BN)   // 32
#define NT 512           // threads per CTA (16 warps = 4/SMSP)
#define NKS 4            // k32-steps

#define LOG2E 1.4426950408889634f
#define CEXP  (30.0f * LOG2E)
#define CLAMP2 (1e-6f * LOG2E)

// ---------------------------------------------------------------------------
// device globals (no allocation allowed)
// ---------------------------------------------------------------------------
__device__ float g_lbl[NR];                         // true label logit (fp32)
__device__ float g_dcorr[NR];                       // exp2 of quantized diag logit (RAW)
__device__ float g_fA[NR];                          // per-row dequant scale
__device__ float g_fB[NS];                          // per-speaker dequant scale
__device__ __align__(16) signed char g_A8[NR * KB]; // int8 rows
__device__ __align__(16) signed char g_B8[NS * KB]; // int8 centroids (pre-scaled 30*log2e)

// ---------------------------------------------------------------------------
// PTX helpers (plain sm_80/90 — safe for compute_103)
// ---------------------------------------------------------------------------
__device__ __forceinline__ uint32_t smem_u32(const void* p) {
    uint32_t a;
    asm("{ .reg .u64 t; cvta.to.shared.u64 t, %1; cvt.u32.u64 %0, t; }" : "=r"(a) : "l"(p));
    return a;
}
#define CP16(dst32, gptr) \
    asm volatile("cp.async.cg.shared.global [%0], [%1], 16;" \
        :: "r"(dst32), "l"(__cvta_generic_to_global(gptr)) : "memory")
#define CP_COMMIT() asm volatile("cp.async.commit_group;" ::: "memory")
#define CP_WAIT0()  asm volatile("cp.async.wait_group 0;" ::: "memory")

__device__ __forceinline__ void ldsm4(unsigned r[4], uint32_t addr) {
    asm volatile("ldmatrix.sync.aligned.m8n8.x4.shared.b16 {%0,%1,%2,%3}, [%4];"
        : "=r"(r[0]), "=r"(r[1]), "=r"(r[2]), "=r"(r[3]) : "r"(addr));
}
__device__ __forceinline__ void imma16832(int d[4], const unsigned a[4],
                                          unsigned b0, unsigned b1) {
    asm volatile("mma.sync.aligned.m16n8k32.row.col.s32.s8.s8.s32 "
        "{%0,%1,%2,%3}, {%4,%5,%6,%7}, {%8,%9}, {%0,%1,%2,%3};"
        : "+r"(d[0]), "+r"(d[1]), "+r"(d[2]), "+r"(d[3])
        : "r"(a[0]), "r"(a[1]), "r"(a[2]), "r"(a[3]), "r"(b0), "r"(b1));
}
__device__ __forceinline__ float2 lds64(uint32_t addr) {
    float2 v;
    asm volatile("ld.shared.v2.f32 {%0,%1}, [%2];" : "=f"(v.x), "=f"(v.y) : "r"(addr));
    return v;
}
__device__ __forceinline__ float wred(float v) {
    #pragma unroll
    for (int off = 16; off > 0; off >>= 1)
        v += __shfl_xor_sync(0xffffffffu, v, off);
    return v;
}
__device__ __forceinline__ float wmax(float v) {
    #pragma unroll
    for (int off = 16; off > 0; off >>= 1)
        v = fmaxf(v, __shfl_xor_sync(0xffffffffu, v, off));
    return v;
}

// ---------------------------------------------------------------------------
// Kernel 1: warp-per-speaker prep, barrier-free. Emits int8 A/B + scales +
// label logits + quantized-exact diagonal correction.
// ---------------------------------------------------------------------------
__global__ void __launch_bounds__(256) prep_kernel(const float* __restrict__ x,
                                                   float* __restrict__ out) {
    const int lane = threadIdx.x & 31;
    const int s = blockIdx.x * 8 + (threadIdx.x >> 5);

    float xv[NG][4];
    {
        const float4* xp = (const float4*)(x + (size_t)s * NG * ND);
        #pragma unroll
        for (int g = 0; g < NG; g++) {
            float4 v = xp[g * 32 + lane];
            xv[g][0] = v.x; xv[g][1] = v.y; xv[g][2] = v.z; xv[g][3] = v.w;
        }
    }

    float xn[NG][4], sumd[4] = {0.f, 0.f, 0.f, 0.f};
    #pragma unroll
    for (int g = 0; g < NG; g++) {
        float n2 = wred(xv[g][0]*xv[g][0] + xv[g][1]*xv[g][1]
                      + xv[g][2]*xv[g][2] + xv[g][3]*xv[g][3]);
        float inv = 1.f / fmaxf(sqrtf(n2), 1e-12f);
        #pragma unroll
        for (int c = 0; c < 4; c++) {
            xn[g][c] = xv[g][c] * inv;
            sumd[c] += xn[g][c];
        }
    }

    float cent[4], centv[4];
    {
        float c2 = 0.f;
        #pragma unroll
        for (int c = 0; c < 4; c++) { cent[c] = sumd[c] * 0.125f; c2 += cent[c]*cent[c]; }
        c2 = wred(c2);
        float sc = (30.f * LOG2E) / fmaxf(sqrtf(c2), 1e-8f);
        #pragma unroll
        for (int c = 0; c < 4; c++) centv[c] = cent[c] * sc;
    }

    // --- B quantization (per speaker) ---
    float mB = wmax(fmaxf(fmaxf(fabsf(centv[0]), fabsf(centv[1])),
                          fmaxf(fabsf(centv[2]), fabsf(centv[3]))));
    float fB = mB * (1.f / 127.f);
    float qb[4];
    {
        float invB = 127.f / mB;
        #pragma unroll
        for (int c = 0; c < 4; c++) qb[c] = rintf(centv[c] * invB);
        char4 b8 = make_char4((signed char)(int)qb[0], (signed char)(int)qb[1],
                              (signed char)(int)qb[2], (signed char)(int)qb[3]);
        *(char4*)&g_B8[(size_t)s * KB + 4 * lane] = b8;
        if (lane == 0) g_fB[s] = fB;
    }

    // --- per-utterance: label logit + A quantization + exact diag corr ---
    #pragma unroll
    for (int g = 0; g < NG; g++) {
        float e[4], e2 = 0.f;
        #pragma unroll
        for (int c = 0; c < 4; c++) {
            e[c] = (sumd[c] - xn[g][c]) * (1.0f / 7.0f);
            e2 += e[c] * e[c];
        }
        e2 = wred(e2);
        float inv = 1.f / fmaxf(sqrtf(e2), 1e-8f);
        float cg = 0.f;
        #pragma unroll
        for (int c = 0; c < 4; c++) cg += xn[g][c] * e[c];
        cg = wred(cg) * inv;

        float mA = wmax(fmaxf(fmaxf(fabsf(xn[g][0]), fabsf(xn[g][1])),
                              fmaxf(fabsf(xn[g][2]), fabsf(xn[g][3]))));
        float fA = mA * (1.f / 127.f);
        float invA = 127.f / mA;
        float qa[4], dq = 0.f;
        #pragma unroll
        for (int c = 0; c < 4; c++) {
            qa[c] = rintf(xn[g][c] * invA);
            dq += qa[c] * qb[c];            // products <= 16129, sum exact in fp32
        }
        dq = wred(dq);

        char4 a8 = make_char4((signed char)(int)qa[0], (signed char)(int)qa[1],
                              (signed char)(int)qa[2], (signed char)(int)qa[3]);
        *(char4*)&g_A8[(size_t)(s * NG + g) * KB + 4 * lane] = a8;

        if (lane == g) {
            g_lbl[s * NG + g]   = fmaxf(30.f * cg, 1e-6f);
            g_fA[s * NG + g]    = fA;
            float l2e = (dq * fA) * fB;     // same arithmetic as GEMM epilogue
            g_dcorr[s * NG + g] = exp2f(fmaxf(l2e, CLAMP2));   // RAW domain
        }
    }

    if (s == 0 && threadIdx.x == 0) out[0] = 0.f;   // zero accumulator
}

// ---------------------------------------------------------------------------
// Kernel 2: IMMA GEMM (int8, m16n8k32, K=128) + fused online log-softmax.
// 128 CTAs x 512 threads. Warp grid 8m x 2n, warp tile 16x32 (afr 16 regs).
// A int8 + fB scales smem-resident; B tiles double-buffered. Epilogue of
// tile t-1 (I2F + dequant + exp2) interleaved into the mma k-loop of tile t.
// Raw exp2 domain (CEXP folded at the end).
// ---------------------------------------------------------------------------
#define SM_A     0                          // 16384 bytes
#define SM_FB    (BM * KB)                  // 16384: 2048 floats = 8192 bytes
#define SM_B0    (SM_FB + NS * 4)           // 24576
#define SM_B1    (SM_B0 + BN * KB)          // 32768
#define SM_TOTAL (SM_B1 + BN * KB)          // 40960
#define BSTRIDE  (BN * KB)                  // 8192 bytes of B per tile

struct TileCtx {
    uint32_t bufB[2];
    uint32_t swzOff[NKS];   // per-k-step swizzle offsets
    uint32_t bOff[2];       // per-n-block row offsets
    const signed char* gptrB;  // this thread's B chunk source
    uint32_t soffB;            // this thread's B chunk smem dest
};

// Compute one 64-col int8 tile into accCur; interleave dequant+exp2 epilogue
// of accPrev (previous tile) between mma groups. prevFB = smem addr of fB
// floats for the previous tile's column-pair of this thread (nj stride 32B).
template <bool HAVE_PREV>
__device__ __forceinline__ void compute_tile(
    const TileCtx& cx, uint32_t bcur,
    unsigned (&afr)[NKS][4],
    int (&accCur)[4][4], int (&accPrev)[4][4],
    float (&zsum)[2], float sA0, float sA1, uint32_t prevFB)
{
    #pragma unroll
    for (int nj = 0; nj < 4; nj++)
        #pragma unroll
        for (int q = 0; q < 4; q++) accCur[nj][q] = 0;

    #pragma unroll
    for (int ks = 0; ks < NKS; ks++) {      // 4 steps: 2 LDSM + 4 imma + 4-val epi
        unsigned bf0[4], bf1[4];
        ldsm4(bf0, bcur + cx.bOff[0] + cx.swzOff[ks]);
        ldsm4(bf1, bcur + cx.bOff[1] + cx.swzOff[ks]);
        imma16832(accCur[0], afr[ks], bf0[0], bf0[1]);
        imma16832(accCur[1], afr[ks], bf0[2], bf0[3]);
        imma16832(accCur[2], afr[ks], bf1[0], bf1[1]);
        imma16832(accCur[3], afr[ks], bf1[2], bf1[3]);

        if (HAVE_PREV) {
            // epilogue group nj = ks of the previous tile
            float2 fb = lds64(prevFB + ks * 32);
            float v0 = ((float)accPrev[ks][0] * sA0) * fb.x;
            float v1 = ((float)accPrev[ks][1] * sA0) * fb.y;
            float v2 = ((float)accPrev[ks][2] * sA1) * fb.x;
            float v3 = ((float)accPrev[ks][3] * sA1) * fb.y;
            zsum[0] += exp2f(fmaxf(v0, CLAMP2)) + exp2f(fmaxf(v1, CLAMP2));
            zsum[1] += exp2f(fmaxf(v2, CLAMP2)) + exp2f(fmaxf(v3, CLAMP2));
        }
    }
}

__global__ void __launch_bounds__(NT, 1) gemm_kernel(float* __restrict__ out) {
    extern __shared__ char smem[];
    __shared__ float zbuf[BM][2];
    __shared__ float red[16];

    const uint32_t sb = smem_u32(smem);
    const int tid  = threadIdx.x;
    const int lane = tid & 31;
    const int wid  = tid >> 5;
    const int wm   = wid & 7;        // 0..7  (16-row slices)
    const int wn   = wid >> 3;       // 0..1  (32-col slices)
    const int br0  = blockIdx.x * BM;

    const signed char* gA = g_A8;
    const signed char* gB = g_B8;

    TileCtx cx;
    // this thread's B chunk (64 rows x 8 chunks = 512 = NT)
    {
        int c = tid & 7, n = tid >> 3;
        cx.soffB = n * KB + ((c ^ (n & 7)) << 4);
        cx.gptrB = gB + (size_t)n * KB + c * 16;
    }

    // ---- prologue: A tile (2 chunks/thread) + fB scales + B tile 0 ----
    #pragma unroll
    for (int ii = 0; ii < 2; ii++) {
        int idx = ii * NT + tid;
        int c = idx & 7, r = idx >> 3;
        CP16(sb + SM_A + r * KB + ((c ^ (r & 7)) << 4),
             gA + (size_t)(br0 + r) * KB + c * 16);
    }
    CP16(sb + SM_FB + tid * 16, (const char*)g_fB + tid * 16);
    CP16(sb + SM_B0 + cx.soffB, cx.gptrB);
    CP_COMMIT();

    // ---- B LDSM addressing ----
    {
        int n0 = wn * 32 + ((lane >> 4) & 1) * 8 + (lane & 7);
        cx.bOff[0] = n0 * KB;
        cx.bOff[1] = (n0 + 16) * KB;
        uint32_t bS = n0 & 7;
        uint32_t cbB = (lane >> 3) & 1;
        #pragma unroll
        for (int ks = 0; ks < NKS; ks++)
            cx.swzOff[ks] = (((2u*ks) | cbB) ^ bS) << 4;
    }
    cx.bufB[0] = sb + SM_B0;
    cx.bufB[1] = sb + SM_B1;

    // row slots + per-row dequant scales
    const int rl0 = wm * 16 + (lane >> 2);
    const float sA0 = g_fA[br0 + rl0];
    const float sA1 = g_fA[br0 + rl0 + 8];
    float zsum[2] = {0.f, 0.f};

    // epilogue fB smem lane base (tile t adds t*256 bytes)
    const uint32_t fbLane = sb + SM_FB + wn * 128 + (lane & 3) * 8;

    // ---- wait for A + B0 + fB, load A fragments (16 regs) ----
    CP_WAIT0();
    __syncthreads();

    unsigned afr[NKS][4];
    {
        const uint32_t cbA = (lane >> 4);
        int row = wm * 16 + (lane & 15);
        uint32_t base = sb + SM_A + row * KB;
        uint32_t s8 = row & 7;
        #pragma unroll
        for (int ks = 0; ks < NKS; ks++)
            ldsm4(afr[ks], base + ((((2u*ks) | cbA) ^ s8) << 4));
    }

    int acc0[4][4], acc1[4][4];

    // tile loop with acc ping-pong; prefetch t+1 each tile
    #define PREFETCH(tn) do { \
        CP16(cx.bufB[(tn) & 1] + cx.soffB, cx.gptrB + (size_t)(tn) * BSTRIDE); \
        CP_COMMIT(); } while (0)
    #define SYNC() do { CP_WAIT0(); __syncthreads(); } while (0)

    PREFETCH(1);
    compute_tile<false>(cx, cx.bufB[0], afr, acc0, acc1, zsum, sA0, sA1, 0);
    SYNC();
    PREFETCH(2);
    compute_tile<true>(cx, cx.bufB[1], afr, acc1, acc0, zsum, sA0, sA1, fbLane);
    SYNC();
    #pragma unroll 1
    for (int t2 = 1; t2 < NTILES / 2 - 1; t2++) {
        PREFETCH(2 * t2 + 1);
        compute_tile<true>(cx, cx.bufB[0], afr, acc0, acc1, zsum, sA0, sA1,
                           fbLane + (2 * t2 - 1) * 256);
        SYNC();
        PREFETCH(2 * t2 + 2);
        compute_tile<true>(cx, cx.bufB[1], afr, acc1, acc0, zsum, sA0, sA1,
                           fbLane + (2 * t2) * 256);
        SYNC();
    }
    PREFETCH(NTILES - 1);
    compute_tile<true>(cx, cx.bufB[0], afr, acc0, acc1, zsum, sA0, sA1,
                       fbLane + (NTILES - 3) * 256);
    SYNC();
    compute_tile<true>(cx, cx.bufB[1], afr, acc1, acc0, zsum, sA0, sA1,
                       fbLane + (NTILES - 2) * 256);

    // tail epilogue: last tile (acc1), fB of tile NTILES-1
    #pragma unroll
    for (int nj = 0; nj < 4; nj++) {
        float2 fb = lds64(fbLane + (NTILES - 1) * 256 + nj * 32);
        float v0 = ((float)acc1[nj][0] * sA0) * fb.x;
        float v1 = ((float)acc1[nj][1] * sA0) * fb.y;
        float v2 = ((float)acc1[nj][2] * sA1) * fb.x;
        float v3 = ((float)acc1[nj][3] * sA1) * fb.y;
        zsum[0] += exp2f(fmaxf(v0, CLAMP2)) + exp2f(fmaxf(v1, CLAMP2));
        zsum[1] += exp2f(fmaxf(v2, CLAMP2)) + exp2f(fmaxf(v3, CLAMP2));
    }

    // reduce across the 4 lanes of each quad (same row)
    #pragma unroll
    for (int sl = 0; sl < 2; sl++) {
        float z = zsum[sl];
        z += __shfl_xor_sync(0xffffffffu, z, 1);
        z += __shfl_xor_sync(0xffffffffu, z, 2);
        if ((lane & 3) == 0) zbuf[rl0 + sl * 8][wn] = z;
    }
    __syncthreads();

    // per-row loss + block reduce + single atomicAdd
    float loss = 0.f;
    if (tid < BM) {
        int row = br0 + tid;
        float lbl = g_lbl[row];
        float Zraw = zbuf[tid][0] + zbuf[tid][1]
                   - g_dcorr[row]
                   + exp2f(lbl * LOG2E);
        float Z = Zraw * exp2f(-CEXP);
        loss = 30.f + logf(Z) - lbl;
    }
    #pragma unroll
    for (int off = 16; off > 0; off >>= 1)
        loss += __shfl_xor_sync(0xffffffffu, loss, off);
    if (lane == 0) red[wid] = loss;
    __syncthreads();
    if (tid == 0) {
        float tot = 0.f;
        #pragma unroll
        for (int q = 0; q < 16; q++) tot += red[q];
        atomicAdd(out, tot * (1.f / (float)NR));
    }
}

// ---------------------------------------------------------------------------
extern "C" void kernel_launch(void* const* d_in, const int* in_sizes, int n_in,
                              void* d_out, int out_size) {
    const float* x = (const float*)d_in[0];
    float* out = (float*)d_out;

    prep_kernel<<<NS / 8, 256>>>(x, out);

    cudaFuncSetAttribute(gemm_kernel, cudaFuncAttributeMaxDynamicSharedMemorySize, SM_TOTAL);
    gemm_kernel<<<NR / BM, NT, SM_TOTAL>>>(out);
}